// round 2
// baseline (speedup 1.0000x reference)
#include <cuda_runtime.h>

#define EPSV     1e-4f
#define TOLSQ    4e-12f        // (2e-6)^2 relative orthogonality threshold
#define MAXSWEEP 24

// One CTA per 64x64 SPD matrix. One-sided Jacobi (SVD of symmetric PSD == eig).
// M stored column-major in shared: M[col*64 + row].
// All pair quantities (dpp, dqq, dpq) computed EXACTLY from live columns each
// visit — no analytic norm tracking (fp32 cancellation noise in tracked norms
// destroys orthogonalization of the near-null subspace; see R1 post-mortem).
__global__ void __launch_bounds__(256, 4)
logm_jacobi_kernel(const float* __restrict__ in, float* __restrict__ out)
{
    __shared__ __align__(16) float M[64 * 64];
    __shared__ float wlog[64];     // log(max(lambda, eps))
    __shared__ int   s_flag;

    const int tid  = threadIdx.x;
    const int lane = tid & 31;
    const int warp = tid >> 5;
    const int sub  = lane >> 4;    // which of 2 pairs this half-warp handles
    const int sl   = lane & 15;    // lane within the 16-lane half
    const size_t base = (size_t)blockIdx.x * 4096;

    // ---- load X (symmetric, so flat row-major copy == column-major) ----
    {
        const float4* g4 = reinterpret_cast<const float4*>(in + base);
        float4* m4 = reinterpret_cast<float4*>(M);
        #pragma unroll
        for (int i = 0; i < 4; ++i) m4[tid + 256 * i] = g4[tid + 256 * i];
    }
    __syncthreads();

    // ---- one-sided Jacobi sweeps ----
    for (int sweep = 0; sweep < MAXSWEEP; ++sweep) {
        if (tid == 0) s_flag = 0;
        __syncthreads();

        for (int r = 0; r < 63; ++r) {
            // 32 disjoint pairs per round (circle method); each warp handles 2
            // pairs simultaneously (16 lanes each, float4/lane), twice (h).
            #pragma unroll
            for (int h = 0; h < 2; ++h) {
                int k = h * 16 + warp * 2 + sub;
                int p, q;
                if (k == 0) { p = 63; q = r; }
                else {
                    p = r + k;      if (p >= 63) p -= 63;
                    q = r + 63 - k; if (q >= 63) q -= 63;
                }
                float4* cp4 = reinterpret_cast<float4*>(M + p * 64) + sl;
                float4* cq4 = reinterpret_cast<float4*>(M + q * 64) + sl;
                float4 ap = *cp4;
                float4 aq = *cq4;

                float dpq = ap.x * aq.x + ap.y * aq.y + ap.z * aq.z + ap.w * aq.w;
                float dpp = ap.x * ap.x + ap.y * ap.y + ap.z * ap.z + ap.w * ap.w;
                float dqq = aq.x * aq.x + aq.y * aq.y + aq.z * aq.z + aq.w * aq.w;
                #pragma unroll
                for (int o = 8; o; o >>= 1) {
                    dpq += __shfl_xor_sync(0xffffffffu, dpq, o);
                    dpp += __shfl_xor_sync(0xffffffffu, dpp, o);
                    dqq += __shfl_xor_sync(0xffffffffu, dqq, o);
                }

                if (dpq * dpq > TOLSQ * dpp * dqq) {
                    if (sl == 0) s_flag = 1;
                    float tau = __fdividef(dqq - dpp, 2.0f * dpq);
                    float t = copysignf(1.0f, tau) /
                              (fabsf(tau) + sqrtf(1.0f + tau * tau));
                    float c = rsqrtf(1.0f + t * t);
                    float s = t * c;
                    float4 np, nq;
                    np.x = c * ap.x - s * aq.x;  np.y = c * ap.y - s * aq.y;
                    np.z = c * ap.z - s * aq.z;  np.w = c * ap.w - s * aq.w;
                    nq.x = s * ap.x + c * aq.x;  nq.y = s * ap.y + c * aq.y;
                    nq.z = s * ap.z + c * aq.z;  nq.w = s * ap.w + c * aq.w;
                    *cp4 = np;
                    *cq4 = nq;
                }
            }
            __syncthreads();
        }

        int active = s_flag;
        __syncthreads();          // protect flag read vs next-sweep reset
        if (!active) break;
    }

    // ---- exact column norms -> eigenvalues; normalize -> eigenvectors ----
    for (int k = warp; k < 64; k += 8) {
        float2 v = *reinterpret_cast<float2*>(M + k * 64 + 2 * lane);
        float ss = v.x * v.x + v.y * v.y;
        #pragma unroll
        for (int o = 16; o; o >>= 1) ss += __shfl_xor_sync(0xffffffffu, ss, o);
        float nrm = sqrtf(ss);
        float inv = (nrm > 0.0f) ? (1.0f / nrm) : 0.0f;
        v.x *= inv; v.y *= inv;
        *reinterpret_cast<float2*>(M + k * 64 + 2 * lane) = v;
        if (lane == 0) wlog[k] = logf(fmaxf(nrm, EPSV));
    }
    __syncthreads();

    // ---- O = U diag(w) U^T, 4x4 register tile per thread ----
    const int ta = tid >> 4;      // tile row block (0..15)
    const int tb = tid & 15;      // tile col block (0..15)
    float acc[4][4];
    #pragma unroll
    for (int i = 0; i < 4; ++i)
        #pragma unroll
        for (int j = 0; j < 4; ++j) acc[i][j] = 0.0f;

    for (int k = 0; k < 64; ++k) {
        float w = wlog[k];
        float4 ur = *reinterpret_cast<const float4*>(M + k * 64 + 4 * ta);
        float4 uc = *reinterpret_cast<const float4*>(M + k * 64 + 4 * tb);
        float r0 = w * ur.x, r1 = w * ur.y, r2 = w * ur.z, r3 = w * ur.w;
        acc[0][0] += r0 * uc.x; acc[0][1] += r0 * uc.y; acc[0][2] += r0 * uc.z; acc[0][3] += r0 * uc.w;
        acc[1][0] += r1 * uc.x; acc[1][1] += r1 * uc.y; acc[1][2] += r1 * uc.z; acc[1][3] += r1 * uc.w;
        acc[2][0] += r2 * uc.x; acc[2][1] += r2 * uc.y; acc[2][2] += r2 * uc.z; acc[2][3] += r2 * uc.w;
        acc[3][0] += r3 * uc.x; acc[3][1] += r3 * uc.y; acc[3][2] += r3 * uc.z; acc[3][3] += r3 * uc.w;
    }

    float* go = out + base;
    #pragma unroll
    for (int i = 0; i < 4; ++i) {
        float4 v = make_float4(acc[i][0], acc[i][1], acc[i][2], acc[i][3]);
        *reinterpret_cast<float4*>(go + (4 * ta + i) * 64 + 4 * tb) = v;
    }
}

extern "C" void kernel_launch(void* const* d_in, const int* in_sizes, int n_in,
                              void* d_out, int out_size)
{
    const float* x = (const float*)d_in[0];
    float* out = (float*)d_out;
    int batches = in_sizes[0] / 4096;   // 64*64 elements per matrix
    logm_jacobi_kernel<<<batches, 256>>>(x, out);
}